// round 13
// baseline (speedup 1.0000x reference)
#include <cuda_runtime.h>
#include <math.h>

#define MAX_B    8192
#define NSPLIT   4
#define NBUCK    4096
#define BSCALE   128.0f       // bucket = int(loss * 128), covers [0, 32)
#define LIST_CAP 1024
#define RANK_CAP 512

__device__ float g_loss[MAX_B];
__device__ int   g_hcnt[NBUCK];          // zero-invariant across calls
__device__ float g_hsum[NBUCK];          // zero-invariant across calls
__device__ int   g_nneg;                 // zero-invariant across calls
__device__ float g_tot;                  // zero-invariant across calls
__device__ float g_pm1[MAX_B * NSPLIT];  // partial top-1 per (row, quarter)
__device__ float g_pm2[MAX_B * NSPLIT];  // partial top-2
__device__ float g_ps [MAX_B * NSPLIT];  // partial expsum
__device__ int   g_rowtick[MAX_B];       // zero-invariant (merger resets)

__device__ __forceinline__ void pdl_trigger() {
    asm volatile("griddepcontrol.launch_dependents;" ::: "memory");
}
__device__ __forceinline__ void pdl_wait() {
    asm volatile("griddepcontrol.wait;" ::: "memory");
}

// ---------------------------------------------------------------------------
// Kernel 1: 4 blocks (320 threads) per row, 32KB quarter each.
// Each block reduces its quarter to (m1, m2, s); the 4th arrival per row
// merges partials in fixed order, computes margin/loss, deposits.
// ---------------------------------------------------------------------------
__global__ __launch_bounds__(320) void npc_row_kernel(
    const float* __restrict__ logits,
    const int*   __restrict__ target,
    int C)
{
    pdl_trigger();

    const int bid = blockIdx.x;
    const int row = bid >> 2;
    const int q   = bid & 3;
    const float* __restrict__ p = logits + (long long)row * (long long)C;
    const int tid = threadIdx.x;

    float m1 = -INFINITY;
    float m2 = -INFINITY;
    float s  = 0.0f;

    const int C4 = C >> 2;
    const int st = (q * C4) >> 2;            // quarter range in float4 units
    const int en = ((q + 1) * C4) >> 2;
    const float4* __restrict__ p4 = (const float4*)p;
#pragma unroll 4
    for (int i = st + tid; i < en; i += 320) {
        float4 v = p4[i];
        float xs[4] = {v.x, v.y, v.z, v.w};
#pragma unroll
        for (int e = 0; e < 4; e++) {
            float x  = xs[e];
            float hi = fmaxf(m1, x);
            float lo = fminf(m1, x);
            m2 = fmaxf(m2, lo);
            m1 = hi;
            s += __expf(x);
        }
    }
    if (q == 3) {                            // scalar tail (C % 4, safety)
        for (int i = (C4 << 2) + tid; i < C; i += 320) {
            float x  = p[i];
            float hi = fmaxf(m1, x);
            float lo = fminf(m1, x);
            m2 = fmaxf(m2, lo);
            m1 = hi;
            s += __expf(x);
        }
    }

#pragma unroll
    for (int o = 16; o > 0; o >>= 1) {
        float om1 = __shfl_xor_sync(0xffffffffu, m1, o);
        float om2 = __shfl_xor_sync(0xffffffffu, m2, o);
        float os  = __shfl_xor_sync(0xffffffffu, s,  o);
        float lo  = fminf(m1, om1);
        m1 = fmaxf(m1, om1);
        m2 = fmaxf(lo, fmaxf(m2, om2));
        s += os;
    }

    __shared__ float sm1[10], sm2[10], ss[10];
    const int warp = tid >> 5;
    const int lane = tid & 31;
    if (lane == 0) { sm1[warp] = m1; sm2[warp] = m2; ss[warp] = s; }
    __syncthreads();

    if (tid == 0) {
        float M1 = sm1[0], M2 = sm2[0], S = ss[0];
        for (int w = 1; w < (320 >> 5); w++) {
            float om1 = sm1[w];
            float lo  = fminf(M1, om1);
            M1 = fmaxf(M1, om1);
            M2 = fmaxf(lo, fmaxf(M2, sm2[w]));
            S += ss[w];
        }

        // publish this quarter's partial, release, take the row ticket
        g_pm1[bid] = M1;
        g_pm2[bid] = M2;
        g_ps [bid] = S;
        __threadfence();
        int old = atomicAdd(&g_rowtick[row], 1);

        if (old == NSPLIT - 1) {
            __threadfence();   // acquire: other quarters' partials visible

            // merge 4 partials in fixed index order (exact for top-2)
            float M1m = -INFINITY, M2m = -INFINITY, Sm = 0.0f;
#pragma unroll
            for (int j = 0; j < NSPLIT; j++) {
                float a = g_pm1[row * NSPLIT + j];
                float b = g_pm2[row * NSPLIT + j];
                float lo = fminf(M1m, a);
                M1m = fmaxf(M1m, a);
                M2m = fmaxf(lo, fmaxf(M2m, b));
                Sm += g_ps[row * NSPLIT + j];
            }

            float tgt = p[target[row]];
            float lse = __logf(Sm);

            float margin1 = tgt - M1m;
            float margin  = (margin1 != 0.0f) ? margin1 : (tgt - M2m);
            float lv = (margin >= 0.0f) ? fmaxf(1.0f - margin, 0.0f)
                                        : fmaxf(1.0f - tgt + lse, 0.0f);
            g_loss[row] = lv;

            int b = (int)(lv * BSCALE);
            b = max(0, min(NBUCK - 1, b));
            atomicAdd(&g_hcnt[b], 1);
            atomicAdd(&g_hsum[b], lv);
            if (margin < 0.0f) atomicAdd(&g_nneg, 1);
            atomicAdd(&g_tot, lv);

            g_rowtick[row] = 0;     // restore zero-invariance
        }
    }
}

// ---------------------------------------------------------------------------
// Kernel 2: PDL-launched, latency-compressed (proven R11 body).
// Mask is a prefix of sorted losses; k = max{k : S_k + k <= thr+2}.
// ---------------------------------------------------------------------------
__global__ __launch_bounds__(1024) void npc_finalize_kernel(
    float* __restrict__ out, int B)
{
    __shared__ float sloss[MAX_B];    // 32 KB staging of g_loss
    __shared__ int   wtc[32];
    __shared__ float wts[32];
    __shared__ float list[LIST_CAP];
    __shared__ float sorted[RANK_CAP];
    __shared__ int   s_bstar, s_k0cnt, s_cntb, s_ln, s_nneg;
    __shared__ float s_S0, s_sumb, s_tot;

    const int tid  = threadIdx.x;
    const int warp = tid >> 5;
    const int lane = tid & 31;

    if (tid == 0) { s_bstar = -1; s_ln = 0; }

    pdl_wait();   // row grid complete + memory visible

    // ---- phase 0: issue ALL global loads together ----
    if (tid == 1) { s_nneg = g_nneg; s_tot = g_tot; g_nneg = 0; g_tot = 0.0f; }

    const int b0 = tid * 4;
    int   hc[4];
    float hs[4];
    int   ci = 0;
    float si = 0.0f;
#pragma unroll
    for (int j = 0; j < 4; j++) {
        hc[j] = g_hcnt[b0 + j];
        hs[j] = g_hsum[b0 + j];
    }

    if (B == MAX_B) {
        const float4* L4 = (const float4*)g_loss;
        float4* S4 = (float4*)sloss;
#pragma unroll
        for (int e = 0; e < 2; e++)
            S4[tid + e * 1024] = L4[tid + e * 1024];
    } else {
        for (int i = tid; i < B; i += 1024) sloss[i] = g_loss[i];
    }

    // zero scratch right behind the reads
#pragma unroll
    for (int j = 0; j < 4; j++) {
        g_hcnt[b0 + j] = 0;
        g_hsum[b0 + j] = 0.0f;
    }

#pragma unroll
    for (int j = 0; j < 4; j++) { ci += hc[j]; si += hs[j]; }

    // ---- hierarchical exclusive pair-scan over thread totals ----
    int   wc = ci;
    float ws = si;
#pragma unroll
    for (int o = 1; o < 32; o <<= 1) {
        int   tc = __shfl_up_sync(0xffffffffu, wc, o);
        float ts = __shfl_up_sync(0xffffffffu, ws, o);
        if (lane >= o) { wc += tc; ws += ts; }
    }
    if (lane == 31) { wtc[warp] = wc; wts[warp] = ws; }
    __syncthreads();
    if (warp == 0) {
        int   tc = wtc[lane];
        float ts = wts[lane];
        int   c2 = tc;
        float s2 = ts;
#pragma unroll
        for (int o = 1; o < 32; o <<= 1) {
            int   uc = __shfl_up_sync(0xffffffffu, c2, o);
            float us = __shfl_up_sync(0xffffffffu, s2, o);
            if (lane >= o) { c2 += uc; s2 += us; }
        }
        wtc[lane] = c2 - tc;
        wts[lane] = s2 - ts;
    }
    __syncthreads();

    const int   nneg      = s_nneg;
    const float total_sum = s_tot;
    const float threshold = 0.81f * (float)B + 0.9f * (float)nneg;
    const float T2        = threshold + 2.0f;
    const bool  all_sel   = ((float)B + total_sum <= T2);

    int   K = wtc[warp] + (wc - ci);
    float S = wts[warp] + (ws - si);

    // ---- locate the unique crossing bucket ----
    if (!all_sel) {
#pragma unroll
        for (int j = 0; j < 4; j++) {
            float before = (float)K + S;
            float after  = (float)(K + hc[j]) + (S + hs[j]);
            if (before <= T2 && after > T2) {
                s_bstar  = b0 + j;
                s_k0cnt  = K;
                s_S0     = S;
                s_cntb   = hc[j];
                s_sumb   = hs[j];
            }
            K += hc[j];
            S += hs[j];
        }
    }
    __syncthreads();

    // ---- gather crossing bucket members from smem staging ----
    const int bstar = s_bstar;
    if (bstar >= 0) {
        for (int i = tid; i < B; i += 1024) {
            float L = sloss[i];
            int b = (int)(L * BSCALE);
            b = max(0, min(NBUCK - 1, b));
            if (b == bstar) {
                int idx = atomicAdd(&s_ln, 1);
                if (idx < LIST_CAP) list[idx] = L;
            }
        }
    }
    __syncthreads();

    const int n = (s_ln < LIST_CAP) ? s_ln : LIST_CAP;

    // ---- parallel rank -> sorted[] ----
    if (bstar >= 0 && n <= RANK_CAP) {
        for (int i = tid; i < n; i += 1024) {
            float xi = list[i];
            int r = 0;
            for (int j = 0; j < n; j++) {
                float xj = list[j];
                r += (xj < xi) || (xj == xi && j < i);
            }
            sorted[r] = xi;
        }
    }
    __syncthreads();

    // ---- boundary resolve ----
    if (warp == 0) {
        if (all_sel || bstar < 0) {
            if (lane == 0) {
                float cntf = (float)B;
                out[0] = fmaxf(total_sum, threshold - cntf) / cntf;
            }
        } else if (n <= 32) {
            float val = (lane < n) ? sorted[lane] : 0.0f;
            float cum = val;
#pragma unroll
            for (int o = 1; o < 32; o <<= 1) {
                float t = __shfl_up_sync(0xffffffffu, cum, o);
                if (lane >= o) cum += t;
            }
            bool sel = (lane < n) &&
                       (s_S0 + cum + (float)(s_k0cnt + lane + 1) <= T2);
            unsigned m = __ballot_sync(0xffffffffu, sel);
            int cnt = __popc(m);
            float Ssel = (cnt > 0) ? __shfl_sync(0xffffffffu, cum, cnt - 1) : 0.0f;
            if (lane == 0) {
                float Sf   = s_S0 + Ssel;
                float cntf = (float)(s_k0cnt + cnt);
                out[0] = fmaxf(Sf, threshold - cntf) / cntf;
            }
        } else if (lane == 0) {
            float Sf, cntf;
            if (n <= RANK_CAP && s_ln <= LIST_CAP) {
                int   k  = s_k0cnt;
                float Sa = s_S0;
                for (int t = 0; t < n; t++) {
                    float val = sorted[t];
                    if (Sa + val + (float)(k + 1) <= T2) { Sa += val; k++; }
                    else break;
                }
                Sf = Sa; cntf = (float)k;
            } else {
                float avg = s_sumb / (float)s_cntb;
                float j = floorf((T2 - s_S0 - (float)s_k0cnt) / (avg + 1.0f));
                j = fmaxf(j, 0.0f);
                j = fminf(j, (float)s_cntb);
                Sf   = s_S0 + j * avg;
                cntf = (float)s_k0cnt + j;
            }
            out[0] = fmaxf(Sf, threshold - cntf) / cntf;
        }
    }
}

// ---------------------------------------------------------------------------
extern "C" void kernel_launch(void* const* d_in, const int* in_sizes, int n_in,
                              void* d_out, int out_size)
{
    const float* logits = (const float*)d_in[0];
    const int*   target = (const int*)d_in[1];
    const int B = in_sizes[1];
    const int C = in_sizes[0] / B;

    npc_row_kernel<<<B * NSPLIT, 320>>>(logits, target, C);

    cudaLaunchConfig_t cfg = {};
    cfg.gridDim  = dim3(1, 1, 1);
    cfg.blockDim = dim3(1024, 1, 1);
    cfg.dynamicSmemBytes = 0;
    cfg.stream = 0;
    cudaLaunchAttribute attr[1];
    attr[0].id = cudaLaunchAttributeProgrammaticStreamSerialization;
    attr[0].val.programmaticStreamSerializationAllowed = 1;
    cfg.attrs = attr;
    cfg.numAttrs = 1;
    cudaLaunchKernelEx(&cfg, npc_finalize_kernel, (float*)d_out, B);
}

// round 14
// speedup vs baseline: 1.1994x; 1.1994x over previous
#include <cuda_runtime.h>
#include <math.h>

#define MAX_B    8192
#define NBUCK    4096
#define BSCALE   128.0f       // bucket = int(loss * 128), covers [0, 32)
#define LIST_CAP 1024
#define RANK_CAP 512

__device__ float g_loss[MAX_B];
__device__ int   g_hcnt[NBUCK];    // zero-invariant across calls
__device__ float g_hsum[NBUCK];    // zero-invariant across calls
__device__ int   g_nneg;           // zero-invariant across calls
__device__ float g_tot;            // zero-invariant across calls

__device__ __forceinline__ void pdl_trigger() {
    asm volatile("griddepcontrol.launch_dependents;" ::: "memory");
}
__device__ __forceinline__ void pdl_wait() {
    asm volatile("griddepcontrol.wait;" ::: "memory");
}

// ---------------------------------------------------------------------------
// Kernel 1: one block (320 threads) per row — proven 148us body + PDL
// trigger. Logit loads use evict-first streaming (__ldcs): data is read
// exactly once, so don't let it churn L2.
// ---------------------------------------------------------------------------
__global__ __launch_bounds__(320) void npc_row_kernel(
    const float* __restrict__ logits,
    const int*   __restrict__ target,
    int C)
{
    pdl_trigger();

    const int row = blockIdx.x;
    const float* __restrict__ p = logits + (long long)row * (long long)C;
    const int tid = threadIdx.x;

    float m1 = -INFINITY;
    float m2 = -INFINITY;
    float s  = 0.0f;

    const int C4 = C >> 2;                      // 8000; 8000/320 = 25 exact
    const float4* __restrict__ p4 = (const float4*)p;
#pragma unroll 5
    for (int i = tid; i < C4; i += 320) {
        float4 v = __ldcs(&p4[i]);
        float xs[4] = {v.x, v.y, v.z, v.w};
#pragma unroll
        for (int e = 0; e < 4; e++) {
            float x  = xs[e];
            float hi = fmaxf(m1, x);
            float lo = fminf(m1, x);
            m2 = fmaxf(m2, lo);
            m1 = hi;
            s += __expf(x);
        }
    }
    for (int i = (C4 << 2) + tid; i < C; i += 320) {   // tail safety
        float x  = __ldcs(&p[i]);
        float hi = fmaxf(m1, x);
        float lo = fminf(m1, x);
        m2 = fmaxf(m2, lo);
        m1 = hi;
        s += __expf(x);
    }

#pragma unroll
    for (int o = 16; o > 0; o >>= 1) {
        float om1 = __shfl_xor_sync(0xffffffffu, m1, o);
        float om2 = __shfl_xor_sync(0xffffffffu, m2, o);
        float os  = __shfl_xor_sync(0xffffffffu, s,  o);
        float lo  = fminf(m1, om1);
        m1 = fmaxf(m1, om1);
        m2 = fmaxf(lo, fmaxf(m2, om2));
        s += os;
    }

    __shared__ float sm1[10], sm2[10], ss[10];
    const int warp = tid >> 5;
    const int lane = tid & 31;
    if (lane == 0) { sm1[warp] = m1; sm2[warp] = m2; ss[warp] = s; }
    __syncthreads();

    if (tid == 0) {
        float M1 = sm1[0], M2 = sm2[0], S = ss[0];
        for (int w = 1; w < (320 >> 5); w++) {
            float om1 = sm1[w];
            float lo  = fminf(M1, om1);
            M1 = fmaxf(M1, om1);
            M2 = fmaxf(lo, fmaxf(M2, sm2[w]));
            S += ss[w];
        }
        float tgt = p[target[row]];
        float lse = __logf(S);

        float margin1 = tgt - M1;
        float margin  = (margin1 != 0.0f) ? margin1 : (tgt - M2);
        float lv = (margin >= 0.0f) ? fmaxf(1.0f - margin, 0.0f)
                                    : fmaxf(1.0f - tgt + lse, 0.0f);
        g_loss[row] = lv;

        int b = (int)(lv * BSCALE);
        b = max(0, min(NBUCK - 1, b));
        atomicAdd(&g_hcnt[b], 1);
        atomicAdd(&g_hsum[b], lv);
        if (margin < 0.0f) atomicAdd(&g_nneg, 1);
        atomicAdd(&g_tot, lv);
    }
}

// ---------------------------------------------------------------------------
// Kernel 2: PDL-launched, latency-compressed (proven R11 body).
//   After pdl_wait: ALL global loads issue together (hist + g_loss->smem +
//   scalars), scratch zeroed behind the reads, smem gather, warp-parallel
//   boundary scan. Mask is a prefix of sorted losses;
//   k = max{k : S_k + k <= thr+2}.
// ---------------------------------------------------------------------------
__global__ __launch_bounds__(1024) void npc_finalize_kernel(
    float* __restrict__ out, int B)
{
    __shared__ float sloss[MAX_B];    // 32 KB staging of g_loss
    __shared__ int   wtc[32];
    __shared__ float wts[32];
    __shared__ float list[LIST_CAP];
    __shared__ float sorted[RANK_CAP];
    __shared__ int   s_bstar, s_k0cnt, s_cntb, s_ln, s_nneg;
    __shared__ float s_S0, s_sumb, s_tot;

    const int tid  = threadIdx.x;
    const int warp = tid >> 5;
    const int lane = tid & 31;

    if (tid == 0) { s_bstar = -1; s_ln = 0; }

    pdl_wait();   // row grid complete + memory visible

    // ---- phase 0: issue ALL global loads together ----
    if (tid == 1) { s_nneg = g_nneg; s_tot = g_tot; g_nneg = 0; g_tot = 0.0f; }

    const int b0 = tid * 4;
    int   hc[4];
    float hs[4];
    int   ci = 0;
    float si = 0.0f;
#pragma unroll
    for (int j = 0; j < 4; j++) {
        hc[j] = g_hcnt[b0 + j];
        hs[j] = g_hsum[b0 + j];
    }

    // g_loss -> smem staging
    if (B == MAX_B) {
        const float4* L4 = (const float4*)g_loss;
        float4* S4 = (float4*)sloss;
#pragma unroll
        for (int e = 0; e < 2; e++)
            S4[tid + e * 1024] = L4[tid + e * 1024];
    } else {
        for (int i = tid; i < B; i += 1024) sloss[i] = g_loss[i];
    }

    // zero scratch right behind the reads
#pragma unroll
    for (int j = 0; j < 4; j++) {
        g_hcnt[b0 + j] = 0;
        g_hsum[b0 + j] = 0.0f;
    }

#pragma unroll
    for (int j = 0; j < 4; j++) { ci += hc[j]; si += hs[j]; }

    // ---- hierarchical exclusive pair-scan over thread totals ----
    int   wc = ci;
    float ws = si;
#pragma unroll
    for (int o = 1; o < 32; o <<= 1) {
        int   tc = __shfl_up_sync(0xffffffffu, wc, o);
        float ts = __shfl_up_sync(0xffffffffu, ws, o);
        if (lane >= o) { wc += tc; ws += ts; }
    }
    if (lane == 31) { wtc[warp] = wc; wts[warp] = ws; }
    __syncthreads();
    if (warp == 0) {
        int   tc = wtc[lane];
        float ts = wts[lane];
        int   c2 = tc;
        float s2 = ts;
#pragma unroll
        for (int o = 1; o < 32; o <<= 1) {
            int   uc = __shfl_up_sync(0xffffffffu, c2, o);
            float us = __shfl_up_sync(0xffffffffu, s2, o);
            if (lane >= o) { c2 += uc; s2 += us; }
        }
        wtc[lane] = c2 - tc;
        wts[lane] = s2 - ts;
    }
    __syncthreads();

    const int   nneg      = s_nneg;
    const float total_sum = s_tot;
    const float threshold = 0.81f * (float)B + 0.9f * (float)nneg;
    const float T2        = threshold + 2.0f;
    const bool  all_sel   = ((float)B + total_sum <= T2);

    int   K = wtc[warp] + (wc - ci);    // exclusive prefix before this thread
    float S = wts[warp] + (ws - si);

    // ---- locate the unique crossing bucket ----
    if (!all_sel) {
#pragma unroll
        for (int j = 0; j < 4; j++) {
            float before = (float)K + S;
            float after  = (float)(K + hc[j]) + (S + hs[j]);
            if (before <= T2 && after > T2) {
                s_bstar  = b0 + j;
                s_k0cnt  = K;
                s_S0     = S;
                s_cntb   = hc[j];
                s_sumb   = hs[j];
            }
            K += hc[j];
            S += hs[j];
        }
    }
    __syncthreads();

    // ---- gather crossing bucket members from smem staging ----
    const int bstar = s_bstar;
    if (bstar >= 0) {
        for (int i = tid; i < B; i += 1024) {
            float L = sloss[i];
            int b = (int)(L * BSCALE);
            b = max(0, min(NBUCK - 1, b));
            if (b == bstar) {
                int idx = atomicAdd(&s_ln, 1);
                if (idx < LIST_CAP) list[idx] = L;
            }
        }
    }
    __syncthreads();

    const int n = (s_ln < LIST_CAP) ? s_ln : LIST_CAP;

    // ---- parallel rank -> sorted[] ----
    if (bstar >= 0 && n <= RANK_CAP) {
        for (int i = tid; i < n; i += 1024) {
            float xi = list[i];
            int r = 0;
            for (int j = 0; j < n; j++) {
                float xj = list[j];
                r += (xj < xi) || (xj == xi && j < i);
            }
            sorted[r] = xi;
        }
    }
    __syncthreads();

    // ---- boundary resolve ----
    if (warp == 0) {
        if (all_sel || bstar < 0) {
            if (lane == 0) {
                float cntf = (float)B;
                out[0] = fmaxf(total_sum, threshold - cntf) / cntf;
            }
        } else if (n <= 32) {
            // warp-parallel prefix test over sorted members
            float val = (lane < n) ? sorted[lane] : 0.0f;
            float cum = val;
#pragma unroll
            for (int o = 1; o < 32; o <<= 1) {
                float t = __shfl_up_sync(0xffffffffu, cum, o);
                if (lane >= o) cum += t;
            }
            bool sel = (lane < n) &&
                       (s_S0 + cum + (float)(s_k0cnt + lane + 1) <= T2);
            unsigned m = __ballot_sync(0xffffffffu, sel);
            int cnt = __popc(m);
            float Ssel = (cnt > 0) ? __shfl_sync(0xffffffffu, cum, cnt - 1) : 0.0f;
            if (lane == 0) {
                float Sf   = s_S0 + Ssel;
                float cntf = (float)(s_k0cnt + cnt);
                out[0] = fmaxf(Sf, threshold - cntf) / cntf;
            }
        } else if (lane == 0) {
            float Sf, cntf;
            if (n <= RANK_CAP && s_ln <= LIST_CAP) {
                int   k  = s_k0cnt;
                float Sa = s_S0;
                for (int t = 0; t < n; t++) {
                    float val = sorted[t];
                    if (Sa + val + (float)(k + 1) <= T2) { Sa += val; k++; }
                    else break;
                }
                Sf = Sa; cntf = (float)k;
            } else {
                float avg = s_sumb / (float)s_cntb;     // near-equal fallback
                float j = floorf((T2 - s_S0 - (float)s_k0cnt) / (avg + 1.0f));
                j = fmaxf(j, 0.0f);
                j = fminf(j, (float)s_cntb);
                Sf   = s_S0 + j * avg;
                cntf = (float)s_k0cnt + j;
            }
            out[0] = fmaxf(Sf, threshold - cntf) / cntf;
        }
    }
}

// ---------------------------------------------------------------------------
extern "C" void kernel_launch(void* const* d_in, const int* in_sizes, int n_in,
                              void* d_out, int out_size)
{
    const float* logits = (const float*)d_in[0];
    const int*   target = (const int*)d_in[1];
    const int B = in_sizes[1];
    const int C = in_sizes[0] / B;

    npc_row_kernel<<<B, 320>>>(logits, target, C);

    cudaLaunchConfig_t cfg = {};
    cfg.gridDim  = dim3(1, 1, 1);
    cfg.blockDim = dim3(1024, 1, 1);
    cfg.dynamicSmemBytes = 0;
    cfg.stream = 0;
    cudaLaunchAttribute attr[1];
    attr[0].id = cudaLaunchAttributeProgrammaticStreamSerialization;
    attr[0].val.programmaticStreamSerializationAllowed = 1;
    cfg.attrs = attr;
    cfg.numAttrs = 1;
    cudaLaunchKernelEx(&cfg, npc_finalize_kernel, (float*)d_out, B);
}